// round 15
// baseline (speedup 1.0000x reference)
#include <cuda_runtime.h>
#include <cuda_fp16.h>

// ---------------------------------------------------------------------------
// GraphSAGE(pool) x3 + BN + classifier — GB300 sm_103a
// Round 15: revert to R12/R13 baseline; fused GEMM gets a merged dual-pass
// pipeline: 6 smem buffers (h x2, ag x2, W1, W2), interleaved k16 loop over
// both terms, 1 wait + 2 syncs per tile, both next-tile stagings overlap the
// merged compute. Standalone agg kernel (full occupancy) restored.
// ---------------------------------------------------------------------------

#define NNODES 100000
#define NEDGES 1000000
#define F      128
#define NCLS   16
#define NEG_SLOPE 0.01f
#define BN_EPS    1e-5f
#define TILE_M 128
#define NTILES ((NNODES + TILE_M - 1) / TILE_M)   // 782
#define GRIDP  152
#define GTH    512

#define ACT_NONE  0
#define ACT_RELU  1
#define ACT_LEAKY 2

typedef unsigned int u32;
typedef unsigned long long u64;

// ------------------------------ scratch -----------------------------------
__device__ __align__(256) __half g_x16[(size_t)NNODES * F];
__device__ __align__(256) __half g_hp [(size_t)NNODES * F];
__device__ __align__(256) __half g_ag [(size_t)NNODES * F];
__device__ __align__(256) __half g_h1 [(size_t)NNODES * F];
__device__ __align__(256) __half g_h2 [(size_t)NNODES * F];
__device__ __align__(256) __half g_wth[9 * F * F];   // transposed [N,K] fp16
__device__ int   g_deg[NNODES];
__device__ int   g_rowptr[NNODES + 1];
__device__ int   g_cursor[NNODES];
__device__ int   g_col[NEDGES];
__device__ float g_sums[2 * F];

// ---------------------- side stream + events (static init) -----------------
struct SideStream {
    cudaStream_t s2 = nullptr;
    cudaEvent_t fork = nullptr, join = nullptr, evw = nullptr;
    SideStream() {
        if (cudaStreamCreateWithFlags(&s2, cudaStreamNonBlocking) != cudaSuccess) s2 = nullptr;
        cudaEventCreateWithFlags(&fork, cudaEventDisableTiming);
        cudaEventCreateWithFlags(&join, cudaEventDisableTiming);
        cudaEventCreateWithFlags(&evw,  cudaEventDisableTiming);
    }
    bool ok() const { return s2 && fork && join && evw; }
};
static SideStream g_ss;

// ------------------------------ helpers -----------------------------------
__device__ __forceinline__ u32 smem_u32(const void* p) {
    u32 a;
    asm("{ .reg .u64 t; cvta.to.shared.u64 t, %1; cvt.u32.u64 %0, t; }"
        : "=r"(a) : "l"(p));
    return a;
}

__device__ __forceinline__ void ldm_x4(u32 addr, u32& r0, u32& r1, u32& r2, u32& r3) {
    asm volatile("ldmatrix.sync.aligned.m8n8.x4.shared.b16 {%0,%1,%2,%3}, [%4];"
                 : "=r"(r0), "=r"(r1), "=r"(r2), "=r"(r3) : "r"(addr));
}

__device__ __forceinline__ void mma16816(float* c, const u32* a, u32 b0, u32 b1) {
    asm volatile("mma.sync.aligned.m16n8k16.row.col.f32.f16.f16.f32 "
                 "{%0,%1,%2,%3}, {%4,%5,%6,%7}, {%8,%9}, {%0,%1,%2,%3};"
                 : "+f"(c[0]), "+f"(c[1]), "+f"(c[2]), "+f"(c[3])
                 : "r"(a[0]), "r"(a[1]), "r"(a[2]), "r"(a[3]), "r"(b0), "r"(b1));
}

__device__ __forceinline__ void cp16(u32 dst, const void* src, int sz) {
    asm volatile("cp.async.cg.shared.global [%0], [%1], 16, %2;"
                 :: "r"(dst), "l"(__cvta_generic_to_global(src)), "r"(sz) : "memory");
}
#define CP_COMMIT() asm volatile("cp.async.commit_group;" ::: "memory")
#define CP_WAIT1()  asm volatile("cp.async.wait_group 1;" ::: "memory")

__device__ __forceinline__ u32 pack_half2(float a, float b) {
    __half2 h = __floats2half2_rn(a, b);
    return *(u32*)&h;
}

// ------------------------------ CSR build ---------------------------------
__global__ void zero_prep() {
    int i = blockIdx.x * blockDim.x + threadIdx.x;
    if (i < NNODES) g_deg[i] = 0;
    if (i < 2 * F)  g_sums[i] = 0.f;
}

__global__ void deg_kernel(const int* __restrict__ dst) {
    int i = blockIdx.x * blockDim.x + threadIdx.x;
    if (i < NEDGES) atomicAdd(&g_deg[dst[i]], 1);
}

__global__ void scan_kernel() {
    __shared__ int sh[1024];
    int t = threadIdx.x;
    const int chunk = (NNODES + 1023) / 1024;
    int beg = t * chunk; if (beg > NNODES) beg = NNODES;
    int end = beg + chunk; if (end > NNODES) end = NNODES;
    int s = 0;
    for (int i = beg; i < end; i++) s += g_deg[i];
    sh[t] = s;
    __syncthreads();
    for (int off = 1; off < 1024; off <<= 1) {
        int v = (t >= off) ? sh[t - off] : 0;
        __syncthreads();
        sh[t] += v;
        __syncthreads();
    }
    int run = (t == 0) ? 0 : sh[t - 1];
    for (int i = beg; i < end; i++) {
        g_rowptr[i] = run;
        g_cursor[i] = run;
        run += g_deg[i];
    }
    if (t == 1023) g_rowptr[NNODES] = sh[1023];
}

__global__ void fill_kernel(const int* __restrict__ src,
                            const int* __restrict__ dst) {
    int i = blockIdx.x * blockDim.x + threadIdx.x;
    if (i < NEDGES) {
        int p = atomicAdd(&g_cursor[dst[i]], 1);
        g_col[p] = src[i];
    }
}

// ------------------------------ packing -----------------------------------
__global__ void pack_x(const float* __restrict__ x, __half* __restrict__ xo) {
    size_t i = (size_t)blockIdx.x * blockDim.x + threadIdx.x;
    size_t total = (size_t)NNODES * F / 4;
    if (i >= total) return;
    float4 v = ((const float4*)x)[i];
    uint2 o;
    o.x = pack_half2(v.x, v.y);
    o.y = pack_half2(v.z, v.w);
    ((uint2*)xo)[i] = o;
}

struct W9 { const float* p[9]; };
__global__ void pack_w_all(W9 w9, __half* __restrict__ oh) {
    int e = blockIdx.x * blockDim.x + threadIdx.x;
    if (e >= F * F) return;
    const float* W = w9.p[blockIdx.y];
    size_t off = (size_t)blockIdx.y * F * F;
    int n = e >> 7, k = e & 127;
    oh[off + e] = __float2half_rn(W[k * F + n]);
}

// ---------------------- segment-max aggregation ----------------------------
__global__ void __launch_bounds__(256) agg_max(const __half* __restrict__ hp,
                                               __half* __restrict__ O) {
    int node = (blockIdx.x * blockDim.x + threadIdx.x) >> 5;
    int lane = threadIdx.x & 31;
    if (node >= NNODES) return;
    int beg = g_rowptr[node];
    int end = g_rowptr[node + 1];
    __half2 a0 = __floats2half2_rn(0.f, 0.f), a1 = a0;
    __half2 b0 = a0, b1 = a0;
    const uint2* hp2 = (const uint2*)hp;
    const u32 full = 0xffffffffu;
    for (int base = beg; base < end; base += 32) {
        int m = end - base; if (m > 32) m = 32;
        int idx = (lane < m) ? g_col[base + lane] : 0;
        int j = 0;
        for (; j + 4 <= m; j += 4) {
            int s0 = __shfl_sync(full, idx, j);
            int s1 = __shfl_sync(full, idx, j + 1);
            int s2 = __shfl_sync(full, idx, j + 2);
            int s3 = __shfl_sync(full, idx, j + 3);
            uint2 v0 = hp2[(size_t)s0 * 32 + lane];
            uint2 v1 = hp2[(size_t)s1 * 32 + lane];
            uint2 v2 = hp2[(size_t)s2 * 32 + lane];
            uint2 v3 = hp2[(size_t)s3 * 32 + lane];
            a0 = __hmax2(a0, *(__half2*)&v0.x);
            a1 = __hmax2(a1, *(__half2*)&v0.y);
            b0 = __hmax2(b0, *(__half2*)&v1.x);
            b1 = __hmax2(b1, *(__half2*)&v1.y);
            a0 = __hmax2(a0, *(__half2*)&v2.x);
            a1 = __hmax2(a1, *(__half2*)&v2.y);
            b0 = __hmax2(b0, *(__half2*)&v3.x);
            b1 = __hmax2(b1, *(__half2*)&v3.y);
        }
        for (; j < m; j++) {
            int s = __shfl_sync(full, idx, j);
            uint2 v = hp2[(size_t)s * 32 + lane];
            a0 = __hmax2(a0, *(__half2*)&v.x);
            a1 = __hmax2(a1, *(__half2*)&v.y);
        }
    }
    a0 = __hmax2(a0, b0);
    a1 = __hmax2(a1, b1);
    uint2 o;
    o.x = *(u32*)&a0;
    o.y = *(u32*)&a1;
    ((uint2*)(O + (size_t)node * F))[lane] = o;
}

// ------------------------- persistent HMMA GEMM ----------------------------
#define RSTRIDE 272
#define TBYTES (128 * RSTRIDE)   // 34816

__device__ __forceinline__ void stage_tile(const __half* __restrict__ src,
                                           u32 dstbase, int row0, int nRows, int tid) {
    #pragma unroll
    for (int i = 0; i < 4; i++) {
        int g = tid + i * GTH;
        int r = g >> 4;
        int j = g & 15;
        int gr = row0 + r;
        int ok = (gr < nRows);
        cp16(dstbase + (u32)r * RSTRIDE + (u32)j * 16,
             src + ((size_t)(ok ? gr : 0) * F + (j << 3)), ok ? 16 : 0);
    }
}

__device__ __forceinline__ void compute_tile(u32 AT, u32 WB,
                                             float acc[2][4][4],
                                             u32 a_row, u32 a_koff,
                                             u32 b_row, u32 b_koff) {
    #pragma unroll
    for (int k16 = 0; k16 < 8; k16++) {
        u32 kbase = (u32)k16 * 32;
        u32 ah[2][4];
        #pragma unroll
        for (int mt = 0; mt < 2; mt++) {
            u32 off = (a_row + mt * 16) * RSTRIDE + kbase + a_koff;
            ldm_x4(AT + off, ah[mt][0], ah[mt][1], ah[mt][2], ah[mt][3]);
        }
        u32 bh[4][2];
        #pragma unroll
        for (int nt2 = 0; nt2 < 2; nt2++) {
            u32 off = (b_row + nt2 * 16) * RSTRIDE + kbase + b_koff;
            ldm_x4(WB + off, bh[2*nt2][0], bh[2*nt2][1], bh[2*nt2+1][0], bh[2*nt2+1][1]);
        }
        #pragma unroll
        for (int mt = 0; mt < 2; mt++)
            #pragma unroll
            for (int nt = 0; nt < 4; nt++)
                mma16816(acc[mt][nt], ah[mt], bh[nt][0], bh[nt][1]);
    }
}

// merged dual-term compute: interleaves (A@W1) and (B@W2) at k16 granularity
__device__ __forceinline__ void compute_tile2(u32 AT, u32 W1B, u32 BT, u32 W2B,
                                              float acc[2][4][4],
                                              u32 a_row, u32 a_koff,
                                              u32 b_row, u32 b_koff) {
    #pragma unroll
    for (int k16 = 0; k16 < 8; k16++) {
        u32 kbase = (u32)k16 * 32;
        // term 1
        {
            u32 ah[2][4];
            #pragma unroll
            for (int mt = 0; mt < 2; mt++) {
                u32 off = (a_row + mt * 16) * RSTRIDE + kbase + a_koff;
                ldm_x4(AT + off, ah[mt][0], ah[mt][1], ah[mt][2], ah[mt][3]);
            }
            u32 bh[4][2];
            #pragma unroll
            for (int nt2 = 0; nt2 < 2; nt2++) {
                u32 off = (b_row + nt2 * 16) * RSTRIDE + kbase + b_koff;
                ldm_x4(W1B + off, bh[2*nt2][0], bh[2*nt2][1], bh[2*nt2+1][0], bh[2*nt2+1][1]);
            }
            #pragma unroll
            for (int mt = 0; mt < 2; mt++)
                #pragma unroll
                for (int nt = 0; nt < 4; nt++)
                    mma16816(acc[mt][nt], ah[mt], bh[nt][0], bh[nt][1]);
        }
        // term 2
        {
            u32 ah[2][4];
            #pragma unroll
            for (int mt = 0; mt < 2; mt++) {
                u32 off = (a_row + mt * 16) * RSTRIDE + kbase + a_koff;
                ldm_x4(BT + off, ah[mt][0], ah[mt][1], ah[mt][2], ah[mt][3]);
            }
            u32 bh[4][2];
            #pragma unroll
            for (int nt2 = 0; nt2 < 2; nt2++) {
                u32 off = (b_row + nt2 * 16) * RSTRIDE + kbase + b_koff;
                ldm_x4(W2B + off, bh[2*nt2][0], bh[2*nt2][1], bh[2*nt2+1][0], bh[2*nt2+1][1]);
            }
            #pragma unroll
            for (int mt = 0; mt < 2; mt++)
                #pragma unroll
                for (int nt = 0; nt < 4; nt++)
                    mma16816(acc[mt][nt], ah[mt], bh[nt][0], bh[nt][1]);
        }
    }
}

// A2==null: out = A@W1 + bias, act (double-buffered A)
// A2!=null: out = A@W1 + A2@W2 + bias, act (both double-buffered, merged loop)
__global__ void __launch_bounds__(GTH, 1) mma_gemm_pers(
    const __half* __restrict__ A,
    const __half* __restrict__ A2,
    const __half* __restrict__ W1, const __half* __restrict__ W2,
    const float* __restrict__ bias,
    __half* __restrict__ C,
    int nRows, int act)
{
    extern __shared__ char dyn[];
    __shared__ float s_bias[F];
    u32 base = smem_u32(dyn);
    const u32 H0 = base,              H1  = base + TBYTES;
    const u32 G0 = base + 2 * TBYTES, G1  = base + 3 * TBYTES;
    const u32 W1B = base + 4 * TBYTES, W2B = base + 5 * TBYTES;

    int tid  = threadIdx.x;
    int wid  = tid >> 5;
    int lane = tid & 31;
    int warp_m = wid & 3;
    int warp_n = wid >> 2;
    bool two = (A2 != nullptr);

    if (tid < F) s_bias[tid] = bias[tid];

    u32 a_row  = (u32)(warp_m * 32) + (lane & 15);
    u32 a_koff = (u32)(lane >> 4) * 16;
    u32 b_row  = (u32)(warp_n * 32) + ((lane >> 4) & 1) * 8 + (lane & 7);
    u32 b_koff = (u32)((lane >> 3) & 1) * 16;

    stage_tile(W1, W1B, 0, F, tid);
    if (two) stage_tile(W2, W2B, 0, F, tid);
    CP_COMMIT();

    int t0 = blockIdx.x;
    int t1 = t0 + GRIDP;
    // prologue: tile t0 group, then tile t1 group
    if (t0 < NTILES) {
        stage_tile(A, H0, t0 * TILE_M, nRows, tid);
        if (two) stage_tile(A2, G0, t0 * TILE_M, nRows, tid);
    }
    CP_COMMIT();
    if (t1 < NTILES) {
        stage_tile(A, H1, t1 * TILE_M, nRows, tid);
        if (two) stage_tile(A2, G1, t1 * TILE_M, nRows, tid);
    }
    CP_COMMIT();

    int it = 0;
    for (int t = t0; t < NTILES; t += GRIDP, it++) {
        float acc[2][4][4];
        #pragma unroll
        for (int mt = 0; mt < 2; mt++)
            #pragma unroll
            for (int nt = 0; nt < 4; nt++)
                #pragma unroll
                for (int q = 0; q < 4; q++) acc[mt][nt][q] = 0.f;

        u32 Hb = (it & 1) ? H1 : H0;
        u32 Gb = (it & 1) ? G1 : G0;
        int tn = t + 2 * GRIDP;

        CP_WAIT1();
        __syncthreads();
        if (two)
            compute_tile2(Hb, W1B, Gb, W2B, acc, a_row, a_koff, b_row, b_koff);
        else
            compute_tile(Hb, W1B, acc, a_row, a_koff, b_row, b_koff);
        __syncthreads();
        if (tn < NTILES) {
            stage_tile(A, Hb, tn * TILE_M, nRows, tid);
            if (two) stage_tile(A2, Gb, tn * TILE_M, nRows, tid);
        }
        CP_COMMIT();

        int row0 = t * TILE_M;
        int rbase = row0 + warp_m * 32 + (lane >> 2);
        int cbase = warp_n * 32 + (lane & 3) * 2;
        #pragma unroll
        for (int mt = 0; mt < 2; mt++) {
            #pragma unroll
            for (int half = 0; half < 2; half++) {
                int grow = rbase + mt * 16 + half * 8;
                if (grow >= nRows) continue;
                #pragma unroll
                for (int nt = 0; nt < 4; nt++) {
                    int col = cbase + nt * 8;
                    float v0 = acc[mt][nt][2 * half]     + s_bias[col];
                    float v1 = acc[mt][nt][2 * half + 1] + s_bias[col + 1];
                    if (act == ACT_RELU) {
                        v0 = fmaxf(v0, 0.f); v1 = fmaxf(v1, 0.f);
                    } else if (act == ACT_LEAKY) {
                        v0 = (v0 > 0.f) ? v0 : v0 * NEG_SLOPE;
                        v1 = (v1 > 0.f) ? v1 : v1 * NEG_SLOPE;
                    }
                    ((u32*)C)[((size_t)grow * F + col) >> 1] = pack_half2(v0, v1);
                }
            }
        }
    }
}

// ------------------------------ BatchNorm ----------------------------------
__global__ void bn_stats(const __half* __restrict__ X) {
    int cp   = threadIdx.x & 63;
    int half = threadIdx.x >> 6;
    float s0 = 0.f, s1 = 0.f, q0 = 0.f, q1 = 0.f;
    for (int r = blockIdx.x * 4 + half; r < NNODES; r += gridDim.x * 4) {
        u32 h = ((const u32*)(X + (size_t)r * F))[cp];
        float2 v = __half22float2(*(__half2*)&h);
        s0 += v.x; q0 += v.x * v.x;
        s1 += v.y; q1 += v.y * v.y;
    }
    __shared__ float sh0[256], sh1[256], sq0[256], sq1[256];
    sh0[threadIdx.x] = s0; sh1[threadIdx.x] = s1;
    sq0[threadIdx.x] = q0; sq1[threadIdx.x] = q1;
    __syncthreads();
    if (half == 0) {
        s0 = sh0[cp] + sh0[cp + 64] + sh0[cp + 128] + sh0[cp + 192];
        s1 = sh1[cp] + sh1[cp + 64] + sh1[cp + 128] + sh1[cp + 192];
        q0 = sq0[cp] + sq0[cp + 64] + sq0[cp + 128] + sq0[cp + 192];
        q1 = sq1[cp] + sq1[cp + 64] + sq1[cp + 128] + sq1[cp + 192];
        atomicAdd(&g_sums[2 * cp],         s0);
        atomicAdd(&g_sums[2 * cp + 1],     s1);
        atomicAdd(&g_sums[F + 2 * cp],     q0);
        atomicAdd(&g_sums[F + 2 * cp + 1], q1);
    }
}

__global__ void bn_apply_leaky(__half* __restrict__ X,
                               const float* __restrict__ gamma,
                               const float* __restrict__ beta) {
    __shared__ float scale[F], shift[F];
    if (threadIdx.x < F) {
        float mu  = g_sums[threadIdx.x] * (1.f / NNODES);
        float var = g_sums[F + threadIdx.x] * (1.f / NNODES) - mu * mu;
        float sc  = rsqrtf(var + BN_EPS) * gamma[threadIdx.x];
        scale[threadIdx.x] = sc;
        shift[threadIdx.x] = beta[threadIdx.x] - mu * sc;
    }
    __syncthreads();
    size_t total = (size_t)NNODES * 16;
    for (size_t i = blockIdx.x * blockDim.x + threadIdx.x; i < total;
         i += (size_t)gridDim.x * blockDim.x) {
        int c = (int)(i & 15) * 8;
        uint4 hv = ((uint4*)X)[i];
        u32 a[4] = {hv.x, hv.y, hv.z, hv.w};
        #pragma unroll
        for (int w = 0; w < 4; w++) {
            float2 v = __half22float2(*(__half2*)&a[w]);
            v.x = v.x * scale[c + 2*w]     + shift[c + 2*w];
            v.y = v.y * scale[c + 2*w + 1] + shift[c + 2*w + 1];
            v.x = (v.x > 0.f) ? v.x : v.x * NEG_SLOPE;
            v.y = (v.y > 0.f) ? v.y : v.y * NEG_SLOPE;
            a[w] = pack_half2(v.x, v.y);
        }
        ((uint4*)X)[i] = make_uint4(a[0], a[1], a[2], a[3]);
    }
}

// ------------------------------ classifier ---------------------------------
__global__ void classifier(const __half* __restrict__ H,
                           const float* __restrict__ wc,
                           const float* __restrict__ bc,
                           float* __restrict__ out) {
    __shared__ float w[F * NCLS];
    __shared__ float b[NCLS];
    for (int i = threadIdx.x; i < F * NCLS; i += blockDim.x) w[i] = wc[i];
    if (threadIdx.x < NCLS) b[threadIdx.x] = bc[threadIdx.x];
    __syncthreads();
    int r = blockIdx.x * blockDim.x + threadIdx.x;
    if (r >= NNODES) return;
    float acc[NCLS];
    #pragma unroll
    for (int j = 0; j < NCLS; j++) acc[j] = 0.f;
    for (int k = 0; k < F; k += 8) {
        uint4 hv = *(const uint4*)(H + (size_t)r * F + k);
        u32 a[4] = {hv.x, hv.y, hv.z, hv.w};
        #pragma unroll
        for (int t = 0; t < 4; t++) {
            float2 v = __half22float2(*(__half2*)&a[t]);
            #pragma unroll
            for (int j = 0; j < NCLS; j++)
                acc[j] += v.x * w[(k + 2*t) * NCLS + j] + v.y * w[(k + 2*t + 1) * NCLS + j];
        }
    }
    #pragma unroll
    for (int j = 0; j < NCLS; j++)
        out[(size_t)r * NCLS + j] = acc[j] + b[j];
}

// ------------------------------ launch -------------------------------------
extern "C" void kernel_launch(void* const* d_in, const int* in_sizes, int n_in,
                              void* d_out, int out_size) {
    const float* x   = (const float*)d_in[0];
    const int*   src = (const int*)  d_in[1];
    const int*   dst = (const int*)  d_in[2];
    const float* wp[3] = { (const float*)d_in[3], (const float*)d_in[8],  (const float*)d_in[13] };
    const float* bp[3] = { (const float*)d_in[4], (const float*)d_in[9],  (const float*)d_in[14] };
    const float* ws[3] = { (const float*)d_in[5], (const float*)d_in[10], (const float*)d_in[15] };
    const float* wn[3] = { (const float*)d_in[6], (const float*)d_in[11], (const float*)d_in[16] };
    const float* bb[3] = { (const float*)d_in[7], (const float*)d_in[12], (const float*)d_in[17] };
    const float* gam = (const float*)d_in[18];
    const float* bet = (const float*)d_in[19];
    const float* wc  = (const float*)d_in[20];
    const float* bc  = (const float*)d_in[21];
    float* out = (float*)d_out;

    __half *x16, *hp, *ag, *h1, *h2, *wth;
    cudaGetSymbolAddress((void**)&x16, g_x16);
    cudaGetSymbolAddress((void**)&hp,  g_hp);
    cudaGetSymbolAddress((void**)&ag,  g_ag);
    cudaGetSymbolAddress((void**)&h1,  g_h1);
    cudaGetSymbolAddress((void**)&h2,  g_h2);
    cudaGetSymbolAddress((void**)&wth, g_wth);

    const int SMEM_DYN = 6 * TBYTES;   // 208896
    cudaFuncSetAttribute(mma_gemm_pers, cudaFuncAttributeMaxDynamicSharedMemorySize, SMEM_DYN);

    const int edgeGrid = (NEDGES + 255) / 256;
    const int aggGrid  = (NNODES * 32 + 255) / 256;
    const int FF = F * F;

    W9 w9;
    for (int i = 0; i < 3; i++) {
        w9.p[3*i]     = wp[i];
        w9.p[3*i + 1] = ws[i];
        w9.p[3*i + 2] = wn[i];
    }

    bool forked = g_ss.ok();
    cudaStream_t s2 = forked ? g_ss.s2 : (cudaStream_t)0;

    // side stream: pack_w then CSR build
    if (forked) {
        cudaEventRecord(g_ss.fork, 0);
        cudaStreamWaitEvent(s2, g_ss.fork, 0);
    }
    pack_w_all<<<dim3(64, 9), 256, 0, s2>>>(w9, wth);
    if (forked) cudaEventRecord(g_ss.evw, s2);
    zero_prep<<<(NNODES + 255) / 256, 256, 0, s2>>>();
    deg_kernel<<<edgeGrid, 256, 0, s2>>>(dst);
    scan_kernel<<<1, 1024, 0, s2>>>();
    fill_kernel<<<edgeGrid, 256, 0, s2>>>(src, dst);
    if (forked) cudaEventRecord(g_ss.join, s2);

    // main: pack_x, then layer0 pool (needs weights)
    pack_x<<<(NNODES * F / 4 + 255) / 256, 256>>>(x, x16);
    if (forked) cudaStreamWaitEvent((cudaStream_t)0, g_ss.evw, 0);
    mma_gemm_pers<<<GRIDP, GTH, SMEM_DYN>>>(
        x16, nullptr, wth, nullptr, bp[0], hp, NNODES, ACT_RELU);

    if (forked) cudaStreamWaitEvent((cudaStream_t)0, g_ss.join, 0);

    const __half* hin = x16;
    __half* hout[3] = { h1, h2, h1 };
    int actOut[3] = { ACT_LEAKY, ACT_NONE, ACT_NONE };

    for (int i = 0; i < 3; i++) {
        if (i > 0) {
            mma_gemm_pers<<<GRIDP, GTH, SMEM_DYN>>>(
                hin, nullptr, wth + (3*i) * FF, nullptr,
                bp[i], hp, NNODES, ACT_RELU);
        }
        agg_max<<<aggGrid, 256>>>(hp, ag);
        mma_gemm_pers<<<GRIDP, GTH, SMEM_DYN>>>(
            hin, ag,
            wth + (3*i + 1) * FF, wth + (3*i + 2) * FF,
            bb[i], hout[i], NNODES, actOut[i]);
        if (i == 1) {
            bn_stats<<<512, 256>>>(h2);
            bn_apply_leaky<<<4096, 256>>>(h2, gam, bet);
        }
        hin = hout[i];
    }

    classifier<<<(NNODES + 255) / 256, 256>>>(h1, wc, bc, out);
}

// round 16
// speedup vs baseline: 1.8906x; 1.8906x over previous
#include <cuda_runtime.h>
#include <cuda_fp16.h>

// ---------------------------------------------------------------------------
// GraphSAGE(pool) x3 + BN + classifier — GB300 sm_103a
// Round 16: R12 structure + PARALLEL 3-phase prefix scan (the old 1-CTA scan
// was 161us of critical path, exposed by the R15 profile). CSR chain now ~40us
// and fully hidden under pack+gemm0 on the main stream.
// ---------------------------------------------------------------------------

#define NNODES 100000
#define NEDGES 1000000
#define F      128
#define NCLS   16
#define NEG_SLOPE 0.01f
#define BN_EPS    1e-5f
#define TILE_M 128
#define NTILES ((NNODES + TILE_M - 1) / TILE_M)   // 782
#define GRIDP  152
#define GTH    512
#define SCAN_BLKS ((NNODES + 255) / 256)          // 391

#define ACT_NONE  0
#define ACT_RELU  1
#define ACT_LEAKY 2

typedef unsigned int u32;
typedef unsigned long long u64;

// ------------------------------ scratch -----------------------------------
__device__ __align__(256) __half g_x16[(size_t)NNODES * F];
__device__ __align__(256) __half g_hp [(size_t)NNODES * F];
__device__ __align__(256) __half g_ag [(size_t)NNODES * F];
__device__ __align__(256) __half g_h1 [(size_t)NNODES * F];
__device__ __align__(256) __half g_h2 [(size_t)NNODES * F];
__device__ __align__(256) __half g_wth[9 * F * F];   // transposed [N,K] fp16
__device__ int   g_deg[NNODES];
__device__ int   g_rowptr[NNODES + 1];
__device__ int   g_cursor[NNODES];
__device__ int   g_col[NEDGES];
__device__ int   g_bsum[SCAN_BLKS];
__device__ int   g_boff[SCAN_BLKS];
__device__ float g_sums[2 * F];

// ---------------------- side stream + events (static init) -----------------
struct SideStream {
    cudaStream_t s2 = nullptr;
    cudaEvent_t fork = nullptr, join = nullptr;
    SideStream() {
        if (cudaStreamCreateWithFlags(&s2, cudaStreamNonBlocking) != cudaSuccess) s2 = nullptr;
        cudaEventCreateWithFlags(&fork, cudaEventDisableTiming);
        cudaEventCreateWithFlags(&join, cudaEventDisableTiming);
    }
    bool ok() const { return s2 && fork && join; }
};
static SideStream g_ss;

// ------------------------------ helpers -----------------------------------
__device__ __forceinline__ u32 smem_u32(const void* p) {
    u32 a;
    asm("{ .reg .u64 t; cvta.to.shared.u64 t, %1; cvt.u32.u64 %0, t; }"
        : "=r"(a) : "l"(p));
    return a;
}

__device__ __forceinline__ void ldm_x4(u32 addr, u32& r0, u32& r1, u32& r2, u32& r3) {
    asm volatile("ldmatrix.sync.aligned.m8n8.x4.shared.b16 {%0,%1,%2,%3}, [%4];"
                 : "=r"(r0), "=r"(r1), "=r"(r2), "=r"(r3) : "r"(addr));
}

__device__ __forceinline__ void mma16816(float* c, const u32* a, u32 b0, u32 b1) {
    asm volatile("mma.sync.aligned.m16n8k16.row.col.f32.f16.f16.f32 "
                 "{%0,%1,%2,%3}, {%4,%5,%6,%7}, {%8,%9}, {%0,%1,%2,%3};"
                 : "+f"(c[0]), "+f"(c[1]), "+f"(c[2]), "+f"(c[3])
                 : "r"(a[0]), "r"(a[1]), "r"(a[2]), "r"(a[3]), "r"(b0), "r"(b1));
}

__device__ __forceinline__ void cp16(u32 dst, const void* src, int sz) {
    asm volatile("cp.async.cg.shared.global [%0], [%1], 16, %2;"
                 :: "r"(dst), "l"(__cvta_generic_to_global(src)), "r"(sz) : "memory");
}
#define CP_COMMIT() asm volatile("cp.async.commit_group;" ::: "memory")
#define CP_WAIT1()  asm volatile("cp.async.wait_group 1;" ::: "memory")

__device__ __forceinline__ u32 pack_half2(float a, float b) {
    __half2 h = __floats2half2_rn(a, b);
    return *(u32*)&h;
}

// ------------------------------ CSR build ---------------------------------
__global__ void zero_prep() {
    int i = blockIdx.x * blockDim.x + threadIdx.x;
    if (i < NNODES) g_deg[i] = 0;
    if (i < 2 * F)  g_sums[i] = 0.f;
}

__global__ void deg_kernel(const int* __restrict__ dst) {
    int i = blockIdx.x * blockDim.x + threadIdx.x;
    if (i < NEDGES) atomicAdd(&g_deg[dst[i]], 1);
}

// phase 1: per-block inclusive scan of 256 degs; store local-exclusive to
// rowptr, block total to g_bsum.
__global__ void scan_p1() {
    __shared__ int sh[256];
    int t = threadIdx.x;
    int i = blockIdx.x * 256 + t;
    int d = (i < NNODES) ? g_deg[i] : 0;
    sh[t] = d;
    __syncthreads();
    #pragma unroll
    for (int off = 1; off < 256; off <<= 1) {
        int v = (t >= off) ? sh[t - off] : 0;
        __syncthreads();
        sh[t] += v;
        __syncthreads();
    }
    if (i < NNODES) g_rowptr[i] = sh[t] - d;   // local exclusive
    if (t == 255) g_bsum[blockIdx.x] = sh[255];
}

// phase 2: 1 block scans the block sums (exclusive offsets).
__global__ void scan_p2() {
    __shared__ int sh[512];
    int t = threadIdx.x;
    int v = (t < SCAN_BLKS) ? g_bsum[t] : 0;
    sh[t] = v;
    __syncthreads();
    #pragma unroll
    for (int off = 1; off < 512; off <<= 1) {
        int u = (t >= off) ? sh[t - off] : 0;
        __syncthreads();
        sh[t] += u;
        __syncthreads();
    }
    if (t < SCAN_BLKS) g_boff[t] = sh[t] - v;  // exclusive
    if (t == 0) g_rowptr[NNODES] = NEDGES;
}

// phase 3: add block offsets; init cursor.
__global__ void scan_p3() {
    int i = blockIdx.x * blockDim.x + threadIdx.x;
    if (i >= NNODES) return;
    int val = g_rowptr[i] + g_boff[i >> 8];
    g_rowptr[i] = val;
    g_cursor[i] = val;
}

__global__ void fill_kernel(const int* __restrict__ src,
                            const int* __restrict__ dst) {
    int i = blockIdx.x * blockDim.x + threadIdx.x;
    if (i < NEDGES) {
        int p = atomicAdd(&g_cursor[dst[i]], 1);
        g_col[p] = src[i];
    }
}

// ------------------------------ packing -----------------------------------
__global__ void pack_x(const float* __restrict__ x, __half* __restrict__ xo) {
    size_t i = (size_t)blockIdx.x * blockDim.x + threadIdx.x;
    size_t total = (size_t)NNODES * F / 4;
    if (i >= total) return;
    float4 v = ((const float4*)x)[i];
    uint2 o;
    o.x = pack_half2(v.x, v.y);
    o.y = pack_half2(v.z, v.w);
    ((uint2*)xo)[i] = o;
}

struct W9 { const float* p[9]; };
__global__ void pack_w_all(W9 w9, __half* __restrict__ oh) {
    int e = blockIdx.x * blockDim.x + threadIdx.x;
    if (e >= F * F) return;
    const float* W = w9.p[blockIdx.y];
    size_t off = (size_t)blockIdx.y * F * F;
    int n = e >> 7, k = e & 127;
    oh[off + e] = __float2half_rn(W[k * F + n]);
}

// ---------------------- segment-max aggregation ----------------------------
__global__ void __launch_bounds__(256) agg_max(const __half* __restrict__ hp,
                                               __half* __restrict__ O) {
    int node = (blockIdx.x * blockDim.x + threadIdx.x) >> 5;
    int lane = threadIdx.x & 31;
    if (node >= NNODES) return;
    int beg = g_rowptr[node];
    int end = g_rowptr[node + 1];
    __half2 a0 = __floats2half2_rn(0.f, 0.f), a1 = a0;
    __half2 b0 = a0, b1 = a0;
    const uint2* hp2 = (const uint2*)hp;
    const u32 full = 0xffffffffu;
    for (int base = beg; base < end; base += 32) {
        int m = end - base; if (m > 32) m = 32;
        int idx = (lane < m) ? g_col[base + lane] : 0;
        int j = 0;
        for (; j + 4 <= m; j += 4) {
            int s0 = __shfl_sync(full, idx, j);
            int s1 = __shfl_sync(full, idx, j + 1);
            int s2 = __shfl_sync(full, idx, j + 2);
            int s3 = __shfl_sync(full, idx, j + 3);
            uint2 v0 = hp2[(size_t)s0 * 32 + lane];
            uint2 v1 = hp2[(size_t)s1 * 32 + lane];
            uint2 v2 = hp2[(size_t)s2 * 32 + lane];
            uint2 v3 = hp2[(size_t)s3 * 32 + lane];
            a0 = __hmax2(a0, *(__half2*)&v0.x);
            a1 = __hmax2(a1, *(__half2*)&v0.y);
            b0 = __hmax2(b0, *(__half2*)&v1.x);
            b1 = __hmax2(b1, *(__half2*)&v1.y);
            a0 = __hmax2(a0, *(__half2*)&v2.x);
            a1 = __hmax2(a1, *(__half2*)&v2.y);
            b0 = __hmax2(b0, *(__half2*)&v3.x);
            b1 = __hmax2(b1, *(__half2*)&v3.y);
        }
        for (; j < m; j++) {
            int s = __shfl_sync(full, idx, j);
            uint2 v = hp2[(size_t)s * 32 + lane];
            a0 = __hmax2(a0, *(__half2*)&v.x);
            a1 = __hmax2(a1, *(__half2*)&v.y);
        }
    }
    a0 = __hmax2(a0, b0);
    a1 = __hmax2(a1, b1);
    uint2 o;
    o.x = *(u32*)&a0;
    o.y = *(u32*)&a1;
    ((uint2*)(O + (size_t)node * F))[lane] = o;
}

// ------------------------- persistent HMMA GEMM ----------------------------
#define RSTRIDE 272
#define TBYTES (128 * RSTRIDE)   // 34816

__device__ __forceinline__ void stage_tile(const __half* __restrict__ src,
                                           u32 dstbase, int row0, int nRows, int tid) {
    #pragma unroll
    for (int i = 0; i < 4; i++) {
        int g = tid + i * GTH;
        int r = g >> 4;
        int j = g & 15;
        int gr = row0 + r;
        int ok = (gr < nRows);
        cp16(dstbase + (u32)r * RSTRIDE + (u32)j * 16,
             src + ((size_t)(ok ? gr : 0) * F + (j << 3)), ok ? 16 : 0);
    }
}

__device__ __forceinline__ void compute_tile(u32 AT, u32 WB,
                                             float acc[2][4][4],
                                             u32 a_row, u32 a_koff,
                                             u32 b_row, u32 b_koff) {
    #pragma unroll
    for (int k16 = 0; k16 < 8; k16++) {
        u32 kbase = (u32)k16 * 32;
        u32 ah[2][4];
        #pragma unroll
        for (int mt = 0; mt < 2; mt++) {
            u32 off = (a_row + mt * 16) * RSTRIDE + kbase + a_koff;
            ldm_x4(AT + off, ah[mt][0], ah[mt][1], ah[mt][2], ah[mt][3]);
        }
        u32 bh[4][2];
        #pragma unroll
        for (int nt2 = 0; nt2 < 2; nt2++) {
            u32 off = (b_row + nt2 * 16) * RSTRIDE + kbase + b_koff;
            ldm_x4(WB + off, bh[2*nt2][0], bh[2*nt2][1], bh[2*nt2+1][0], bh[2*nt2+1][1]);
        }
        #pragma unroll
        for (int mt = 0; mt < 2; mt++)
            #pragma unroll
            for (int nt = 0; nt < 4; nt++)
                mma16816(acc[mt][nt], ah[mt], bh[nt][0], bh[nt][1]);
    }
}

// A2==null: out = A@W1 + bias, act (double-buffered A)
// A2!=null: out = A@W1 + A2@W2 + bias, act (sequential dual pass, R12 proven)
__global__ void __launch_bounds__(GTH, 1) mma_gemm_pers(
    const __half* __restrict__ A,
    const __half* __restrict__ A2,
    const __half* __restrict__ W1, const __half* __restrict__ W2,
    const float* __restrict__ bias,
    __half* __restrict__ C,
    int nRows, int act)
{
    extern __shared__ char dyn[];
    __shared__ float s_bias[F];
    u32 base = smem_u32(dyn);
    const u32 A0 = base, A1 = base + TBYTES;
    const u32 W1B = base + 2 * TBYTES, W2B = base + 3 * TBYTES;

    int tid  = threadIdx.x;
    int wid  = tid >> 5;
    int lane = tid & 31;
    int warp_m = wid & 3;
    int warp_n = wid >> 2;
    bool two = (A2 != nullptr);

    if (tid < F) s_bias[tid] = bias[tid];

    u32 a_row  = (u32)(warp_m * 32) + (lane & 15);
    u32 a_koff = (u32)(lane >> 4) * 16;
    u32 b_row  = (u32)(warp_n * 32) + ((lane >> 4) & 1) * 8 + (lane & 7);
    u32 b_koff = (u32)((lane >> 3) & 1) * 16;

    stage_tile(W1, W1B, 0, F, tid);
    if (two) stage_tile(W2, W2B, 0, F, tid);
    CP_COMMIT();

    int t0 = blockIdx.x;
    if (two) {
        if (t0 < NTILES) stage_tile(A,  A0, t0 * TILE_M, nRows, tid);
        CP_COMMIT();
        if (t0 < NTILES) stage_tile(A2, A1, t0 * TILE_M, nRows, tid);
        CP_COMMIT();
    } else {
        if (t0 < NTILES) stage_tile(A, A0, t0 * TILE_M, nRows, tid);
        CP_COMMIT();
        int t1 = t0 + GRIDP;
        if (t1 < NTILES) stage_tile(A, A1, t1 * TILE_M, nRows, tid);
        CP_COMMIT();
    }

    int it = 0;
    for (int t = t0; t < NTILES; t += GRIDP, it++) {
        float acc[2][4][4];
        #pragma unroll
        for (int mt = 0; mt < 2; mt++)
            #pragma unroll
            for (int nt = 0; nt < 4; nt++)
                #pragma unroll
                for (int q = 0; q < 4; q++) acc[mt][nt][q] = 0.f;

        if (two) {
            int tn = t + GRIDP;
            CP_WAIT1();
            __syncthreads();
            compute_tile(A0, W1B, acc, a_row, a_koff, b_row, b_koff);
            __syncthreads();
            if (tn < NTILES) stage_tile(A, A0, tn * TILE_M, nRows, tid);
            CP_COMMIT();
            CP_WAIT1();
            __syncthreads();
            compute_tile(A1, W2B, acc, a_row, a_koff, b_row, b_koff);
            __syncthreads();
            if (tn < NTILES) stage_tile(A2, A1, tn * TILE_M, nRows, tid);
            CP_COMMIT();
        } else {
            u32 Abuf = (it & 1) ? A1 : A0;
            int tn = t + 2 * GRIDP;
            CP_WAIT1();
            __syncthreads();
            compute_tile(Abuf, W1B, acc, a_row, a_koff, b_row, b_koff);
            __syncthreads();
            if (tn < NTILES) stage_tile(A, Abuf, tn * TILE_M, nRows, tid);
            CP_COMMIT();
        }

        int row0 = t * TILE_M;
        int rbase = row0 + warp_m * 32 + (lane >> 2);
        int cbase = warp_n * 32 + (lane & 3) * 2;
        #pragma unroll
        for (int mt = 0; mt < 2; mt++) {
            #pragma unroll
            for (int half = 0; half < 2; half++) {
                int grow = rbase + mt * 16 + half * 8;
                if (grow >= nRows) continue;
                #pragma unroll
                for (int nt = 0; nt < 4; nt++) {
                    int col = cbase + nt * 8;
                    float v0 = acc[mt][nt][2 * half]     + s_bias[col];
                    float v1 = acc[mt][nt][2 * half + 1] + s_bias[col + 1];
                    if (act == ACT_RELU) {
                        v0 = fmaxf(v0, 0.f); v1 = fmaxf(v1, 0.f);
                    } else if (act == ACT_LEAKY) {
                        v0 = (v0 > 0.f) ? v0 : v0 * NEG_SLOPE;
                        v1 = (v1 > 0.f) ? v1 : v1 * NEG_SLOPE;
                    }
                    ((u32*)C)[((size_t)grow * F + col) >> 1] = pack_half2(v0, v1);
                }
            }
        }
    }
}

// ------------------------------ BatchNorm ----------------------------------
__global__ void bn_stats(const __half* __restrict__ X) {
    int cp   = threadIdx.x & 63;
    int half = threadIdx.x >> 6;
    float s0 = 0.f, s1 = 0.f, q0 = 0.f, q1 = 0.f;
    for (int r = blockIdx.x * 4 + half; r < NNODES; r += gridDim.x * 4) {
        u32 h = ((const u32*)(X + (size_t)r * F))[cp];
        float2 v = __half22float2(*(__half2*)&h);
        s0 += v.x; q0 += v.x * v.x;
        s1 += v.y; q1 += v.y * v.y;
    }
    __shared__ float sh0[256], sh1[256], sq0[256], sq1[256];
    sh0[threadIdx.x] = s0; sh1[threadIdx.x] = s1;
    sq0[threadIdx.x] = q0; sq1[threadIdx.x] = q1;
    __syncthreads();
    if (half == 0) {
        s0 = sh0[cp] + sh0[cp + 64] + sh0[cp + 128] + sh0[cp + 192];
        s1 = sh1[cp] + sh1[cp + 64] + sh1[cp + 128] + sh1[cp + 192];
        q0 = sq0[cp] + sq0[cp + 64] + sq0[cp + 128] + sq0[cp + 192];
        q1 = sq1[cp] + sq1[cp + 64] + sq1[cp + 128] + sq1[cp + 192];
        atomicAdd(&g_sums[2 * cp],         s0);
        atomicAdd(&g_sums[2 * cp + 1],     s1);
        atomicAdd(&g_sums[F + 2 * cp],     q0);
        atomicAdd(&g_sums[F + 2 * cp + 1], q1);
    }
}

__global__ void bn_apply_leaky(__half* __restrict__ X,
                               const float* __restrict__ gamma,
                               const float* __restrict__ beta) {
    __shared__ float scale[F], shift[F];
    if (threadIdx.x < F) {
        float mu  = g_sums[threadIdx.x] * (1.f / NNODES);
        float var = g_sums[F + threadIdx.x] * (1.f / NNODES) - mu * mu;
        float sc  = rsqrtf(var + BN_EPS) * gamma[threadIdx.x];
        scale[threadIdx.x] = sc;
        shift[threadIdx.x] = beta[threadIdx.x] - mu * sc;
    }
    __syncthreads();
    size_t total = (size_t)NNODES * 16;
    for (size_t i = blockIdx.x * blockDim.x + threadIdx.x; i < total;
         i += (size_t)gridDim.x * blockDim.x) {
        int c = (int)(i & 15) * 8;
        uint4 hv = ((uint4*)X)[i];
        u32 a[4] = {hv.x, hv.y, hv.z, hv.w};
        #pragma unroll
        for (int w = 0; w < 4; w++) {
            float2 v = __half22float2(*(__half2*)&a[w]);
            v.x = v.x * scale[c + 2*w]     + shift[c + 2*w];
            v.y = v.y * scale[c + 2*w + 1] + shift[c + 2*w + 1];
            v.x = (v.x > 0.f) ? v.x : v.x * NEG_SLOPE;
            v.y = (v.y > 0.f) ? v.y : v.y * NEG_SLOPE;
            a[w] = pack_half2(v.x, v.y);
        }
        ((uint4*)X)[i] = make_uint4(a[0], a[1], a[2], a[3]);
    }
}

// ------------------------------ classifier ---------------------------------
__global__ void classifier(const __half* __restrict__ H,
                           const float* __restrict__ wc,
                           const float* __restrict__ bc,
                           float* __restrict__ out) {
    __shared__ float w[F * NCLS];
    __shared__ float b[NCLS];
    for (int i = threadIdx.x; i < F * NCLS; i += blockDim.x) w[i] = wc[i];
    if (threadIdx.x < NCLS) b[threadIdx.x] = bc[threadIdx.x];
    __syncthreads();
    int r = blockIdx.x * blockDim.x + threadIdx.x;
    if (r >= NNODES) return;
    float acc[NCLS];
    #pragma unroll
    for (int j = 0; j < NCLS; j++) acc[j] = 0.f;
    for (int k = 0; k < F; k += 8) {
        uint4 hv = *(const uint4*)(H + (size_t)r * F + k);
        u32 a[4] = {hv.x, hv.y, hv.z, hv.w};
        #pragma unroll
        for (int t = 0; t < 4; t++) {
            float2 v = __half22float2(*(__half2*)&a[t]);
            #pragma unroll
            for (int j = 0; j < NCLS; j++)
                acc[j] += v.x * w[(k + 2*t) * NCLS + j] + v.y * w[(k + 2*t + 1) * NCLS + j];
        }
    }
    #pragma unroll
    for (int j = 0; j < NCLS; j++)
        out[(size_t)r * NCLS + j] = acc[j] + b[j];
}

// ------------------------------ launch -------------------------------------
extern "C" void kernel_launch(void* const* d_in, const int* in_sizes, int n_in,
                              void* d_out, int out_size) {
    const float* x   = (const float*)d_in[0];
    const int*   src = (const int*)  d_in[1];
    const int*   dst = (const int*)  d_in[2];
    const float* wp[3] = { (const float*)d_in[3], (const float*)d_in[8],  (const float*)d_in[13] };
    const float* bp[3] = { (const float*)d_in[4], (const float*)d_in[9],  (const float*)d_in[14] };
    const float* ws[3] = { (const float*)d_in[5], (const float*)d_in[10], (const float*)d_in[15] };
    const float* wn[3] = { (const float*)d_in[6], (const float*)d_in[11], (const float*)d_in[16] };
    const float* bb[3] = { (const float*)d_in[7], (const float*)d_in[12], (const float*)d_in[17] };
    const float* gam = (const float*)d_in[18];
    const float* bet = (const float*)d_in[19];
    const float* wc  = (const float*)d_in[20];
    const float* bc  = (const float*)d_in[21];
    float* out = (float*)d_out;

    __half *x16, *hp, *ag, *h1, *h2, *wth;
    cudaGetSymbolAddress((void**)&x16, g_x16);
    cudaGetSymbolAddress((void**)&hp,  g_hp);
    cudaGetSymbolAddress((void**)&ag,  g_ag);
    cudaGetSymbolAddress((void**)&h1,  g_h1);
    cudaGetSymbolAddress((void**)&h2,  g_h2);
    cudaGetSymbolAddress((void**)&wth, g_wth);

    const int SMEM_DYN = 4 * TBYTES;   // 139264
    cudaFuncSetAttribute(mma_gemm_pers, cudaFuncAttributeMaxDynamicSharedMemorySize, SMEM_DYN);

    const int edgeGrid = (NEDGES + 255) / 256;
    const int aggGrid  = (NNODES * 32 + 255) / 256;
    const int FF = F * F;

    W9 w9;
    for (int i = 0; i < 3; i++) {
        w9.p[3*i]     = wp[i];
        w9.p[3*i + 1] = ws[i];
        w9.p[3*i + 2] = wn[i];
    }

    bool forked = g_ss.ok();
    cudaStream_t s2 = forked ? g_ss.s2 : (cudaStream_t)0;

    // CSR build on side stream (now fully parallel scan)
    if (forked) {
        cudaEventRecord(g_ss.fork, 0);
        cudaStreamWaitEvent(s2, g_ss.fork, 0);
    }
    zero_prep<<<(NNODES + 255) / 256, 256, 0, s2>>>();
    deg_kernel<<<edgeGrid, 256, 0, s2>>>(dst);
    scan_p1<<<SCAN_BLKS, 256, 0, s2>>>();
    scan_p2<<<1, 512, 0, s2>>>();
    scan_p3<<<SCAN_BLKS, 256, 0, s2>>>();
    fill_kernel<<<edgeGrid, 256, 0, s2>>>(src, dst);
    if (forked) cudaEventRecord(g_ss.join, s2);

    // main: packs + layer0 pool GEMM (overlaps CSR build)
    pack_x<<<(NNODES * F / 4 + 255) / 256, 256>>>(x, x16);
    pack_w_all<<<dim3(64, 9), 256>>>(w9, wth);
    mma_gemm_pers<<<GRIDP, GTH, SMEM_DYN>>>(
        x16, nullptr, wth, nullptr, bp[0], hp, NNODES, ACT_RELU);

    if (forked) cudaStreamWaitEvent((cudaStream_t)0, g_ss.join, 0);

    const __half* hin = x16;
    __half* hout[3] = { h1, h2, h1 };
    int actOut[3] = { ACT_LEAKY, ACT_NONE, ACT_NONE };

    for (int i = 0; i < 3; i++) {
        if (i > 0) {
            mma_gemm_pers<<<GRIDP, GTH, SMEM_DYN>>>(
                hin, nullptr, wth + (3*i) * FF, nullptr,
                bp[i], hp, NNODES, ACT_RELU);
        }
        agg_max<<<aggGrid, 256>>>(hp, ag);
        mma_gemm_pers<<<GRIDP, GTH, SMEM_DYN>>>(
            hin, ag,
            wth + (3*i + 1) * FF, wth + (3*i + 2) * FF,
            bb[i], hout[i], NNODES, actOut[i]);
        if (i == 1) {
            bn_stats<<<512, 256>>>(h2);
            bn_apply_leaky<<<4096, 256>>>(h2, gam, bet);
        }
        hin = hout[i];
    }

    classifier<<<(NNODES + 255) / 256, 256>>>(h1, wc, bc, out);
}